// round 15
// baseline (speedup 1.0000x reference)
#include <cuda_runtime.h>
#include <cuda_bf16.h>
#include <cstdint>

// Fixed shapes for this registry entry
#define MAX_N 100000
#define MAX_T 3
#define D 128
#define MAX_E 800000

// Scratch (allocation-free rule: __device__ globals)
__device__ int   g_dcnt[MAX_T * MAX_N];                 // in-degree per (t, dst)
__device__ float g_dis[MAX_T * MAX_N];                  // rsqrt(deg+1)
__device__ int   g_offs[MAX_T * MAX_N];                 // CSR row offsets
__device__ int   g_cur[MAX_T * MAX_N];                  // fill cursors
__device__ int   g_slist[MAX_T * MAX_E];                // bucketed src indices
__device__ int   g_bsum[512];
__device__ int   g_bexcl[512];

// ---------------------------------------------------------------------------
__global__ void k_deg_zero(int* dcnt, int n) {
    int i = blockIdx.x * blockDim.x + threadIdx.x;
    if (i < n) dcnt[i] = 0;
}

__global__ void k_deg_count(const int* __restrict__ edges, int* __restrict__ dcnt,
                            int N, int E, int T) {
    int i = blockIdx.x * blockDim.x + threadIdx.x;
    int total = T * E;
    if (i >= total) return;
    int t = i / E;
    int e = i - t * E;
    int d = __ldg(edges + (size_t)t * 2 * E + E + e);   // dst
    atomicAdd(dcnt + t * N + d, 1);
}

__global__ void k_dis(const int* __restrict__ dcnt, float* __restrict__ dis, int n) {
    int i = blockIdx.x * blockDim.x + threadIdx.x;
    if (i < n) dis[i] = rsqrtf((float)(dcnt[i] + 1));
}

// ---------------------------------------------------------------------------
// Exclusive scan of dcnt -> offs.  1024 elements / block.
__global__ void k_scan_reduce(const int* __restrict__ dcnt, int* __restrict__ bsum, int n) {
    __shared__ int sh[256];
    int tid = threadIdx.x;
    int base = blockIdx.x * 1024 + tid * 4;
    int s = 0;
#pragma unroll
    for (int j = 0; j < 4; j++) if (base + j < n) s += dcnt[base + j];
    sh[tid] = s;
    __syncthreads();
    for (int off = 128; off > 0; off >>= 1) {
        if (tid < off) sh[tid] += sh[tid + off];
        __syncthreads();
    }
    if (tid == 0) bsum[blockIdx.x] = sh[0];
}

__global__ void k_scan_bsum(const int* __restrict__ bsum, int* __restrict__ bexcl, int nblk) {
    __shared__ int sh[512];
    int tid = threadIdx.x;
    int v = (tid < nblk) ? bsum[tid] : 0;
    sh[tid] = v;
    __syncthreads();
    for (int off = 1; off < 512; off <<= 1) {
        int t = 0;
        if (tid >= off) t = sh[tid - off];
        __syncthreads();
        sh[tid] += t;
        __syncthreads();
    }
    if (tid < nblk) bexcl[tid] = sh[tid] - v;
}

__global__ void k_scan_final(const int* __restrict__ dcnt, const int* __restrict__ bexcl,
                             int* __restrict__ offs, int* __restrict__ cur, int n) {
    __shared__ int sh[256];
    int tid = threadIdx.x;
    int base = blockIdx.x * 1024 + tid * 4;
    int v[4];
#pragma unroll
    for (int j = 0; j < 4; j++) v[j] = (base + j < n) ? dcnt[base + j] : 0;
    int tsum = v[0] + v[1] + v[2] + v[3];
    sh[tid] = tsum;
    __syncthreads();
    for (int off = 1; off < 256; off <<= 1) {
        int t = 0;
        if (tid >= off) t = sh[tid - off];
        __syncthreads();
        sh[tid] += t;
        __syncthreads();
    }
    int excl = sh[tid] - tsum + bexcl[blockIdx.x];
#pragma unroll
    for (int j = 0; j < 4; j++) {
        if (base + j < n) { offs[base + j] = excl; cur[base + j] = excl; }
        excl += v[j];
    }
}

// ---------------------------------------------------------------------------
__global__ void k_fill(const int* __restrict__ edges, int* __restrict__ cur,
                       int* __restrict__ slist, int N, int E, int T) {
    int i = blockIdx.x * blockDim.x + threadIdx.x;
    int total = T * E;
    if (i >= total) return;
    int t = i / E;
    int e = i - t * E;
    const int* srcp = edges + (size_t)t * 2 * E;
    int s = __ldg(srcp + e);
    int d = __ldg(srcp + E + e);
    int pos = atomicAdd(cur + t * N + d, 1);
    slist[pos] = s;
}

// ---------------------------------------------------------------------------
// Fused gather + split-bf16 tensor-core GEMM.
// Block owns 128 output rows. For each relation t: gather the 128 aggregated
// rows (CSR, no atomics) straight into smem as bf16 hi/lo, then mma against
// W[t] (hi/lo staged per 32-k tile), accumulating fp32 fragments across t.
// A*W ~= Ahi*Whi + Ahi*Wlo + Alo*Whi  (drops Alo*Wlo ~ 2^-16 relative).
#define LDA 136   // bf16 elems per A smem row (128 data + 8 pad; 272B stride -> conflict-free ldmatrix)
#define LDW 136   // bf16 elems per W smem row

#define SM_AHI 0
#define SM_ALO (128 * LDA)
#define SM_WHI (2 * 128 * LDA)
#define SM_WLO (2 * 128 * LDA + 32 * LDW)
#define SM_BS  (2 * 128 * LDA + 2 * 32 * LDW)           // float[128] after bf16 area
#define SMEM_BYTES (SM_BS * 2 + 128 * 4)

__device__ __forceinline__ void mma_bf16(float* c, const uint32_t* a, const uint32_t* b) {
    asm volatile(
        "mma.sync.aligned.m16n8k16.row.col.f32.bf16.bf16.f32 "
        "{%0,%1,%2,%3}, {%4,%5,%6,%7}, {%8,%9}, {%0,%1,%2,%3};"
        : "+f"(c[0]), "+f"(c[1]), "+f"(c[2]), "+f"(c[3])
        : "r"(a[0]), "r"(a[1]), "r"(a[2]), "r"(a[3]), "r"(b[0]), "r"(b[1]));
}

__device__ __forceinline__ uint32_t smem_u32(const void* p) {
    return (uint32_t)__cvta_generic_to_shared(p);
}

__device__ __forceinline__ void ldsm_x4(uint32_t* r, uint32_t addr) {
    asm volatile("ldmatrix.sync.aligned.m8n8.x4.shared.b16 {%0,%1,%2,%3}, [%4];"
                 : "=r"(r[0]), "=r"(r[1]), "=r"(r[2]), "=r"(r[3]) : "r"(addr));
}

__device__ __forceinline__ void ldsm_x4_t(uint32_t* r, uint32_t addr) {
    asm volatile("ldmatrix.sync.aligned.m8n8.x4.trans.shared.b16 {%0,%1,%2,%3}, [%4];"
                 : "=r"(r[0]), "=r"(r[1]), "=r"(r[2]), "=r"(r[3]) : "r"(addr));
}

__device__ __forceinline__ void split_pair(float a, float b,
                                           __nv_bfloat162* hi, __nv_bfloat162* lo) {
    __nv_bfloat16 ha = __float2bfloat16(a);
    __nv_bfloat16 hb = __float2bfloat16(b);
    __nv_bfloat16 la = __float2bfloat16(a - __bfloat162float(ha));
    __nv_bfloat16 lb = __float2bfloat16(b - __bfloat162float(hb));
    *hi = __halves2bfloat162(ha, hb);
    *lo = __halves2bfloat162(la, lb);
}

__global__ void __launch_bounds__(256, 2)
k_fused(const float* __restrict__ x, const float* __restrict__ dis,
        const int* __restrict__ offs, const int* __restrict__ dcnt,
        const int* __restrict__ slist, const float* __restrict__ W,
        const float* __restrict__ b, float* __restrict__ out, int N, int T) {
    extern __shared__ char smraw[];
    __nv_bfloat16* sAhi = (__nv_bfloat16*)smraw + SM_AHI;
    __nv_bfloat16* sAlo = (__nv_bfloat16*)smraw + SM_ALO;
    __nv_bfloat16* sWhi = (__nv_bfloat16*)smraw + SM_WHI;
    __nv_bfloat16* sWlo = (__nv_bfloat16*)smraw + SM_WLO;
    float* bs = (float*)(smraw + SM_BS * 2);

    const int tid  = threadIdx.x;
    const int wid  = tid >> 5;
    const int lane = tid & 31;
    const int wm   = wid & 3;        // warp row in mma phase (32 rows each)
    const int wn   = wid >> 2;       // warp col (64 cols each)
    const int g    = lane >> 2;
    const int tg   = lane & 3;
    const int R0   = blockIdx.x * 128;

    if (tid < 128) {
        float s = 0.f;
        for (int t = 0; t < T; t++) s += __ldg(b + t * 128 + tid);
        bs[tid] = s;
    }

    float acc[2][8][4];
#pragma unroll
    for (int mb = 0; mb < 2; mb++)
#pragma unroll
        for (int nf = 0; nf < 8; nf++)
#pragma unroll
            for (int j = 0; j < 4; j++) acc[mb][nf][j] = 0.f;

    // ldmatrix lane-address components
    const int lm   = lane >> 3;
    const int lr   = lane & 7;
    const int a_r  = (lm & 1) * 8 + lr;
    const int a_c8 = (lm >> 1) * 8;
    const int w_kr = (lm & 1) * 8 + lr;
    const int w_n8 = (lm >> 1) * 8;

    for (int t = 0; t < T; t++) {
        // ---- gather phase: warp handles 16 rows; CSR accumulate in regs,
        //      split fp32 -> bf16 hi/lo straight into smem A tile.
        __syncthreads();   // previous mma done reading sA
#pragma unroll 1
        for (int i = 0; i < 16; i++) {
            int r = wid * 16 + i;
            int d = R0 + r;
            float4 a4 = make_float4(0.f, 0.f, 0.f, 0.f);
            if (d < N) {
                int gi = t * N + d;
                float dd  = __ldg(dis + gi);
                int   off = __ldg(offs + gi);
                int   deg = __ldg(dcnt + gi);
                a4 = __ldg((const float4*)x + (size_t)d * 32 + lane);
                a4.x *= dd; a4.y *= dd; a4.z *= dd; a4.w *= dd;   // self-loop
                for (int base = 0; base < deg; base += 32) {
                    int   myS = 0;
                    float myW = 0.f;
                    int m = deg - base; if (m > 32) m = 32;
                    if (lane < m) {
                        myS = __ldg(slist + off + base + lane);
                        myW = __ldg(dis + t * N + myS);
                    }
                    for (int j = 0; j < m; j++) {
                        int   s = __shfl_sync(0xffffffffu, myS, j);
                        float w = __shfl_sync(0xffffffffu, myW, j);
                        float4 v = __ldg((const float4*)x + (size_t)s * 32 + lane);
                        a4.x += w * v.x; a4.y += w * v.y;
                        a4.z += w * v.z; a4.w += w * v.w;
                    }
                }
                a4.x *= dd; a4.y *= dd; a4.z *= dd; a4.w *= dd;
            }
            __nv_bfloat162 h0, l0, h1, l1;
            split_pair(a4.x, a4.y, &h0, &l0);
            split_pair(a4.z, a4.w, &h1, &l1);
            __nv_bfloat162* ph = (__nv_bfloat162*)&sAhi[r * LDA + lane * 4];
            __nv_bfloat162* pl = (__nv_bfloat162*)&sAlo[r * LDA + lane * 4];
            ph[0] = h0; ph[1] = h1;
            pl[0] = l0; pl[1] = l1;
        }
        __syncthreads();

        // ---- mma phase over k tiles of 32
        const float* Wt = W + (size_t)t * 128 * 128;
        for (int kt = 0; kt < 4; kt++) {
            if (kt) __syncthreads();   // previous kt done reading sW
            // stage W k-tile 32x128 fp32 -> hi/lo bf16
#pragma unroll
            for (int it = 0; it < 4; it++) {
                int idx = tid + it * 256;           // 0..1023
                int row = idx >> 5, c4 = idx & 31;  // 32 float4 per row
                float4 v = __ldg((const float4*)(Wt + (size_t)(kt * 32 + row) * 128) + c4);
                __nv_bfloat162 h0, l0, h1, l1;
                split_pair(v.x, v.y, &h0, &l0);
                split_pair(v.z, v.w, &h1, &l1);
                __nv_bfloat162* ph = (__nv_bfloat162*)&sWhi[row * LDW + c4 * 4];
                __nv_bfloat162* pl = (__nv_bfloat162*)&sWlo[row * LDW + c4 * 4];
                ph[0] = h0; ph[1] = h1;
                pl[0] = l0; pl[1] = l1;
            }
            __syncthreads();

#pragma unroll
            for (int ks = 0; ks < 2; ks++) {
                uint32_t ahi[2][4], alo[2][4];
#pragma unroll
                for (int mb = 0; mb < 2; mb++) {
                    int row = wm * 32 + mb * 16 + a_r;
                    int col = kt * 32 + ks * 16 + a_c8;
                    ldsm_x4(ahi[mb], smem_u32(&sAhi[row * LDA + col]));
                    ldsm_x4(alo[mb], smem_u32(&sAlo[row * LDA + col]));
                }
#pragma unroll
                for (int np = 0; np < 4; np++) {
                    int krow = ks * 16 + w_kr;
                    int ncol = wn * 64 + np * 16 + w_n8;
                    uint32_t bh[4], bl[4];
                    ldsm_x4_t(bh, smem_u32(&sWhi[krow * LDW + ncol]));
                    ldsm_x4_t(bl, smem_u32(&sWlo[krow * LDW + ncol]));
#pragma unroll
                    for (int mb = 0; mb < 2; mb++) {
                        mma_bf16(acc[mb][np * 2],     ahi[mb], bh);
                        mma_bf16(acc[mb][np * 2],     ahi[mb], bl);
                        mma_bf16(acc[mb][np * 2],     alo[mb], bh);
                        mma_bf16(acc[mb][np * 2 + 1], ahi[mb], bh + 2);
                        mma_bf16(acc[mb][np * 2 + 1], ahi[mb], bl + 2);
                        mma_bf16(acc[mb][np * 2 + 1], alo[mb], bh + 2);
                    }
                }
            }
        }
    }

    // epilogue: bias + store
#pragma unroll
    for (int mb = 0; mb < 2; mb++) {
        int row0 = R0 + wm * 32 + mb * 16 + g;
        int row1 = row0 + 8;
#pragma unroll
        for (int nf = 0; nf < 8; nf++) {
            int col = wn * 64 + nf * 8 + tg * 2;
            float bx = bs[col], by = bs[col + 1];
            if (row0 < N) {
                float2 v0 = make_float2(acc[mb][nf][0] + bx, acc[mb][nf][1] + by);
                *(float2*)(out + (size_t)row0 * 128 + col) = v0;
            }
            if (row1 < N) {
                float2 v1 = make_float2(acc[mb][nf][2] + bx, acc[mb][nf][3] + by);
                *(float2*)(out + (size_t)row1 * 128 + col) = v1;
            }
        }
    }
}

// ---------------------------------------------------------------------------
extern "C" void kernel_launch(void* const* d_in, const int* in_sizes, int n_in,
                              void* d_out, int out_size) {
    const float* x     = (const float*)d_in[0];   // [N, 128]
    const int*   edges = (const int*)d_in[1];     // [T, 2, E]
    const float* W     = (const float*)d_in[2];   // [T, 128, 128]
    const float* b     = (const float*)d_in[3];   // [T, 128]
    float* out = (float*)d_out;                   // [N, 128]

    const int N = in_sizes[0] / D;
    const int T = in_sizes[3] / D;
    const int E = in_sizes[1] / (2 * T);

    float* dis = nullptr;
    int *dcnt = nullptr, *offs = nullptr, *cur = nullptr, *slist = nullptr;
    int *bsum = nullptr, *bexcl = nullptr;
    cudaGetSymbolAddress((void**)(&dcnt),  g_dcnt);
    cudaGetSymbolAddress((void**)(&dis),   g_dis);
    cudaGetSymbolAddress((void**)(&offs),  g_offs);
    cudaGetSymbolAddress((void**)(&cur),   g_cur);
    cudaGetSymbolAddress((void**)(&slist), g_slist);
    cudaGetSymbolAddress((void**)(&bsum),  g_bsum);
    cudaGetSymbolAddress((void**)(&bexcl), g_bexcl);

    const int n    = T * N;
    const int nblk = (n + 1023) / 1024;

    k_deg_zero<<<(n + 255) / 256, 256>>>(dcnt, n);
    {
        int total = T * E;
        k_deg_count<<<(total + 255) / 256, 256>>>(edges, dcnt, N, E, T);
    }
    k_dis<<<(n + 255) / 256, 256>>>(dcnt, dis, n);
    k_scan_reduce<<<nblk, 256>>>(dcnt, bsum, n);
    k_scan_bsum<<<1, 512>>>(bsum, bexcl, nblk);
    k_scan_final<<<nblk, 256>>>(dcnt, bexcl, offs, cur, n);
    {
        int total = T * E;
        k_fill<<<(total + 255) / 256, 256>>>(edges, cur, slist, N, E, T);
    }
    // fused gather + split-bf16 mma GEMM + bias
    static bool attr_set = false;
    if (!attr_set) {
        cudaFuncSetAttribute(k_fused, cudaFuncAttributeMaxDynamicSharedMemorySize,
                             SMEM_BYTES);
        attr_set = true;
    }
    k_fused<<<(N + 127) / 128, 256, SMEM_BYTES>>>(x, dis, offs, dcnt, slist,
                                                  W, b, out, N, T);
}

// round 16
// speedup vs baseline: 1.2376x; 1.2376x over previous
#include <cuda_runtime.h>
#include <cuda_bf16.h>
#include <cstdint>

// Fixed shapes for this registry entry
#define MAX_N 100000
#define MAX_T 3
#define D 128
#define MAX_E 800000

// Scratch (allocation-free rule: __device__ globals)
__device__ float g_agg[(size_t)MAX_T * MAX_N * D];      // 153.6 MB aggregated features
__device__ int   g_dcnt[MAX_T * MAX_N];                 // in-degree per (t, dst)
__device__ float g_dis[MAX_T * MAX_N];                  // rsqrt(deg+1)
__device__ int   g_offs[MAX_T * MAX_N];                 // CSR row offsets
__device__ int   g_cur[MAX_T * MAX_N];                  // fill cursors
__device__ int   g_slist[MAX_T * MAX_E];                // bucketed src indices
__device__ int   g_bsum[512];
__device__ int   g_bexcl[512];

// ---------------------------------------------------------------------------
__global__ void k_deg_zero(int* dcnt, int n) {
    int i = blockIdx.x * blockDim.x + threadIdx.x;
    if (i < n) dcnt[i] = 0;
}

__global__ void k_deg_count(const int* __restrict__ edges, int* __restrict__ dcnt,
                            int N, int E, int T) {
    int i = blockIdx.x * blockDim.x + threadIdx.x;
    int total = T * E;
    if (i >= total) return;
    int t = i / E;
    int e = i - t * E;
    int d = __ldg(edges + (size_t)t * 2 * E + E + e);   // dst
    atomicAdd(dcnt + t * N + d, 1);
}

// ---------------------------------------------------------------------------
// Exclusive scan of dcnt -> offs.  1024 elements / block.
__global__ void k_scan_reduce(const int* __restrict__ dcnt, int* __restrict__ bsum, int n) {
    __shared__ int sh[256];
    int tid = threadIdx.x;
    int base = blockIdx.x * 1024 + tid * 4;
    int s = 0;
#pragma unroll
    for (int j = 0; j < 4; j++) if (base + j < n) s += dcnt[base + j];
    sh[tid] = s;
    __syncthreads();
    for (int off = 128; off > 0; off >>= 1) {
        if (tid < off) sh[tid] += sh[tid + off];
        __syncthreads();
    }
    if (tid == 0) bsum[blockIdx.x] = sh[0];
}

__global__ void k_scan_bsum(const int* __restrict__ bsum, int* __restrict__ bexcl, int nblk) {
    __shared__ int sh[512];
    int tid = threadIdx.x;
    int v = (tid < nblk) ? bsum[tid] : 0;
    sh[tid] = v;
    __syncthreads();
    for (int off = 1; off < 512; off <<= 1) {
        int t = 0;
        if (tid >= off) t = sh[tid - off];
        __syncthreads();
        sh[tid] += t;
        __syncthreads();
    }
    if (tid < nblk) bexcl[tid] = sh[tid] - v;
}

// scan final + fused dis = rsqrt(deg+1)
__global__ void k_scan_final(const int* __restrict__ dcnt, const int* __restrict__ bexcl,
                             int* __restrict__ offs, int* __restrict__ cur,
                             float* __restrict__ dis, int n) {
    __shared__ int sh[256];
    int tid = threadIdx.x;
    int base = blockIdx.x * 1024 + tid * 4;
    int v[4];
#pragma unroll
    for (int j = 0; j < 4; j++) v[j] = (base + j < n) ? dcnt[base + j] : 0;
    int tsum = v[0] + v[1] + v[2] + v[3];
    sh[tid] = tsum;
    __syncthreads();
    for (int off = 1; off < 256; off <<= 1) {
        int t = 0;
        if (tid >= off) t = sh[tid - off];
        __syncthreads();
        sh[tid] += t;
        __syncthreads();
    }
    int excl = sh[tid] - tsum + bexcl[blockIdx.x];
#pragma unroll
    for (int j = 0; j < 4; j++) {
        if (base + j < n) {
            offs[base + j] = excl;
            cur[base + j]  = excl;
            dis[base + j]  = rsqrtf((float)(v[j] + 1));
        }
        excl += v[j];
    }
}

// ---------------------------------------------------------------------------
__global__ void k_fill(const int* __restrict__ edges, int* __restrict__ cur,
                       int* __restrict__ slist, int N, int E, int T) {
    int i = blockIdx.x * blockDim.x + threadIdx.x;
    int total = T * E;
    if (i >= total) return;
    int t = i / E;
    int e = i - t * E;
    const int* srcp = edges + (size_t)t * 2 * E;
    int s = __ldg(srcp + e);
    int d = __ldg(srcp + E + e);
    int pos = atomicAdd(cur + t * N + d, 1);
    slist[pos] = s;
}

// ---------------------------------------------------------------------------
// One warp per (t, dst): agg[t][d] = dis[d] * ( dis[d]*x[d] + sum_s dis[s]*x[s] )
// Inner loop 4-way unrolled: 4 independent LDG.128 in flight before consumers.
__global__ void k_gather(const float* __restrict__ x, const float* __restrict__ dis,
                         const int* __restrict__ offs, const int* __restrict__ dcnt,
                         const int* __restrict__ slist, float* __restrict__ agg,
                         int N, int T) {
    int gw   = (blockIdx.x * blockDim.x + threadIdx.x) >> 5;
    int lane = threadIdx.x & 31;
    int total = T * N;
    if (gw >= total) return;
    int t = gw / N;
    int d = gw - t * N;

    float dd  = __ldg(dis + gw);
    int   off = __ldg(offs + gw);
    int   deg = __ldg(dcnt + gw);
    const float* dis_t = dis + t * N;

    float4 acc = __ldg((const float4*)x + (size_t)d * 32 + lane);
    acc.x *= dd; acc.y *= dd; acc.z *= dd; acc.w *= dd;   // self-loop pre-scale

    for (int base = 0; base < deg; base += 32) {
        int   myS = 0;
        float myW = 0.f;
        int m = deg - base; if (m > 32) m = 32;
        if (lane < m) {
            myS = __ldg(slist + off + base + lane);
            myW = __ldg(dis_t + myS);
        }
        int j = 0;
        for (; j + 4 <= m; j += 4) {
            int s0 = __shfl_sync(0xffffffffu, myS, j);
            int s1 = __shfl_sync(0xffffffffu, myS, j + 1);
            int s2 = __shfl_sync(0xffffffffu, myS, j + 2);
            int s3 = __shfl_sync(0xffffffffu, myS, j + 3);
            float w0 = __shfl_sync(0xffffffffu, myW, j);
            float w1 = __shfl_sync(0xffffffffu, myW, j + 1);
            float w2 = __shfl_sync(0xffffffffu, myW, j + 2);
            float w3 = __shfl_sync(0xffffffffu, myW, j + 3);
            float4 v0 = __ldg((const float4*)x + (size_t)s0 * 32 + lane);
            float4 v1 = __ldg((const float4*)x + (size_t)s1 * 32 + lane);
            float4 v2 = __ldg((const float4*)x + (size_t)s2 * 32 + lane);
            float4 v3 = __ldg((const float4*)x + (size_t)s3 * 32 + lane);
            acc.x += w0 * v0.x; acc.y += w0 * v0.y; acc.z += w0 * v0.z; acc.w += w0 * v0.w;
            acc.x += w1 * v1.x; acc.y += w1 * v1.y; acc.z += w1 * v1.z; acc.w += w1 * v1.w;
            acc.x += w2 * v2.x; acc.y += w2 * v2.y; acc.z += w2 * v2.z; acc.w += w2 * v2.w;
            acc.x += w3 * v3.x; acc.y += w3 * v3.y; acc.z += w3 * v3.z; acc.w += w3 * v3.w;
        }
        for (; j < m; j++) {
            int   s = __shfl_sync(0xffffffffu, myS, j);
            float w = __shfl_sync(0xffffffffu, myW, j);
            float4 v = __ldg((const float4*)x + (size_t)s * 32 + lane);
            acc.x += w * v.x; acc.y += w * v.y; acc.z += w * v.z; acc.w += w * v.w;
        }
    }
    acc.x *= dd; acc.y *= dd; acc.z *= dd; acc.w *= dd;
    ((float4*)agg)[(size_t)gw * 32 + lane] = acc;
}

// ---------------------------------------------------------------------------
// Split-bf16 tensor-core GEMM: out = sum_t agg[t] @ W[t] + sum_t b[t]
// A*W ~= Ahi*Whi + Ahi*Wlo + Alo*Whi  (drops Alo*Wlo ~ 2^-16 relative).
#define LDA 40    // bf16 elems per A smem row (32 data + 8 pad -> conflict-free)
#define LDW 136   // bf16 elems per W smem row (128 data + 8 pad)

__device__ __forceinline__ void mma_bf16(float* c, const uint32_t* a, const uint32_t* b) {
    asm volatile(
        "mma.sync.aligned.m16n8k16.row.col.f32.bf16.bf16.f32 "
        "{%0,%1,%2,%3}, {%4,%5,%6,%7}, {%8,%9}, {%0,%1,%2,%3};"
        : "+f"(c[0]), "+f"(c[1]), "+f"(c[2]), "+f"(c[3])
        : "r"(a[0]), "r"(a[1]), "r"(a[2]), "r"(a[3]), "r"(b[0]), "r"(b[1]));
}

__device__ __forceinline__ uint32_t smem_u32(const void* p) {
    return (uint32_t)__cvta_generic_to_shared(p);
}

__device__ __forceinline__ void ldsm_x4(uint32_t* r, uint32_t addr) {
    asm volatile("ldmatrix.sync.aligned.m8n8.x4.shared.b16 {%0,%1,%2,%3}, [%4];"
                 : "=r"(r[0]), "=r"(r[1]), "=r"(r[2]), "=r"(r[3]) : "r"(addr));
}

__device__ __forceinline__ void ldsm_x4_t(uint32_t* r, uint32_t addr) {
    asm volatile("ldmatrix.sync.aligned.m8n8.x4.trans.shared.b16 {%0,%1,%2,%3}, [%4];"
                 : "=r"(r[0]), "=r"(r[1]), "=r"(r[2]), "=r"(r[3]) : "r"(addr));
}

__device__ __forceinline__ void split_pair(float a, float b,
                                           __nv_bfloat162* hi, __nv_bfloat162* lo) {
    __nv_bfloat16 ha = __float2bfloat16(a);
    __nv_bfloat16 hb = __float2bfloat16(b);
    __nv_bfloat16 la = __float2bfloat16(a - __bfloat162float(ha));
    __nv_bfloat16 lb = __float2bfloat16(b - __bfloat162float(hb));
    *hi = __halves2bfloat162(ha, hb);
    *lo = __halves2bfloat162(la, lb);
}

__global__ void __launch_bounds__(256, 2)
k_gemm_mma(const float* __restrict__ agg, const float* __restrict__ W,
           const float* __restrict__ b, float* __restrict__ out, int N, int T) {
    __shared__ __nv_bfloat16 sAhi[128 * LDA];
    __shared__ __nv_bfloat16 sAlo[128 * LDA];
    __shared__ __nv_bfloat16 sWhi[32 * LDW];
    __shared__ __nv_bfloat16 sWlo[32 * LDW];
    __shared__ float bs[128];

    const int tid  = threadIdx.x;
    const int wid  = tid >> 5;
    const int lane = tid & 31;
    const int wm   = wid & 3;
    const int wn   = wid >> 2;
    const int g    = lane >> 2;
    const int tg   = lane & 3;
    const int R0   = blockIdx.x * 128;

    if (tid < 128) {
        float s = 0.f;
        for (int t = 0; t < T; t++) s += __ldg(b + t * 128 + tid);
        bs[tid] = s;
    }

    float acc[2][8][4];
#pragma unroll
    for (int mb = 0; mb < 2; mb++)
#pragma unroll
        for (int nf = 0; nf < 8; nf++)
#pragma unroll
            for (int j = 0; j < 4; j++) acc[mb][nf][j] = 0.f;

    const int lm   = lane >> 3;
    const int lr   = lane & 7;
    const int a_r  = (lm & 1) * 8 + lr;
    const int a_c8 = (lm >> 1) * 8;
    const int w_kr = (lm & 1) * 8 + lr;
    const int w_n8 = (lm >> 1) * 8;

    for (int t = 0; t < T; t++) {
        const float* At = agg + (size_t)t * N * 128;
        const float* Wt = W + (size_t)t * 128 * 128;
        for (int kt = 0; kt < 4; kt++) {
            __syncthreads();
#pragma unroll
            for (int it = 0; it < 4; it++) {
                int idx = tid + it * 256;
                int row = idx >> 3, c4 = idx & 7;
                float4 v = make_float4(0.f, 0.f, 0.f, 0.f);
                if (R0 + row < N)
                    v = __ldg((const float4*)(At + (size_t)(R0 + row) * 128 + kt * 32) + c4);
                __nv_bfloat162 h0, l0, h1, l1;
                split_pair(v.x, v.y, &h0, &l0);
                split_pair(v.z, v.w, &h1, &l1);
                __nv_bfloat162* ph = (__nv_bfloat162*)&sAhi[row * LDA + c4 * 4];
                __nv_bfloat162* pl = (__nv_bfloat162*)&sAlo[row * LDA + c4 * 4];
                ph[0] = h0; ph[1] = h1;
                pl[0] = l0; pl[1] = l1;
            }
#pragma unroll
            for (int it = 0; it < 4; it++) {
                int idx = tid + it * 256;
                int row = idx >> 5, c4 = idx & 31;
                float4 v = __ldg((const float4*)(Wt + (size_t)(kt * 32 + row) * 128) + c4);
                __nv_bfloat162 h0, l0, h1, l1;
                split_pair(v.x, v.y, &h0, &l0);
                split_pair(v.z, v.w, &h1, &l1);
                __nv_bfloat162* ph = (__nv_bfloat162*)&sWhi[row * LDW + c4 * 4];
                __nv_bfloat162* pl = (__nv_bfloat162*)&sWlo[row * LDW + c4 * 4];
                ph[0] = h0; ph[1] = h1;
                pl[0] = l0; pl[1] = l1;
            }
            __syncthreads();

#pragma unroll
            for (int ks = 0; ks < 2; ks++) {
                uint32_t ahi[2][4], alo[2][4];
#pragma unroll
                for (int mb = 0; mb < 2; mb++) {
                    int row = wm * 32 + mb * 16 + a_r;
                    int col = ks * 16 + a_c8;
                    ldsm_x4(ahi[mb], smem_u32(&sAhi[row * LDA + col]));
                    ldsm_x4(alo[mb], smem_u32(&sAlo[row * LDA + col]));
                }
#pragma unroll
                for (int np = 0; np < 4; np++) {
                    int krow = ks * 16 + w_kr;
                    int ncol = wn * 64 + np * 16 + w_n8;
                    uint32_t bh[4], bl[4];
                    ldsm_x4_t(bh, smem_u32(&sWhi[krow * LDW + ncol]));
                    ldsm_x4_t(bl, smem_u32(&sWlo[krow * LDW + ncol]));
#pragma unroll
                    for (int mb = 0; mb < 2; mb++) {
                        mma_bf16(acc[mb][np * 2],     ahi[mb], bh);
                        mma_bf16(acc[mb][np * 2],     ahi[mb], bl);
                        mma_bf16(acc[mb][np * 2],     alo[mb], bh);
                        mma_bf16(acc[mb][np * 2 + 1], ahi[mb], bh + 2);
                        mma_bf16(acc[mb][np * 2 + 1], ahi[mb], bl + 2);
                        mma_bf16(acc[mb][np * 2 + 1], alo[mb], bh + 2);
                    }
                }
            }
        }
    }

#pragma unroll
    for (int mb = 0; mb < 2; mb++) {
        int row0 = R0 + wm * 32 + mb * 16 + g;
        int row1 = row0 + 8;
#pragma unroll
        for (int nf = 0; nf < 8; nf++) {
            int col = wn * 64 + nf * 8 + tg * 2;
            float bx = bs[col], by = bs[col + 1];
            if (row0 < N) {
                float2 v0 = make_float2(acc[mb][nf][0] + bx, acc[mb][nf][1] + by);
                *(float2*)(out + (size_t)row0 * 128 + col) = v0;
            }
            if (row1 < N) {
                float2 v1 = make_float2(acc[mb][nf][2] + bx, acc[mb][nf][3] + by);
                *(float2*)(out + (size_t)row1 * 128 + col) = v1;
            }
        }
    }
}

// ---------------------------------------------------------------------------
extern "C" void kernel_launch(void* const* d_in, const int* in_sizes, int n_in,
                              void* d_out, int out_size) {
    const float* x     = (const float*)d_in[0];   // [N, 128]
    const int*   edges = (const int*)d_in[1];     // [T, 2, E]
    const float* W     = (const float*)d_in[2];   // [T, 128, 128]
    const float* b     = (const float*)d_in[3];   // [T, 128]
    float* out = (float*)d_out;                   // [N, 128]

    const int N = in_sizes[0] / D;
    const int T = in_sizes[3] / D;
    const int E = in_sizes[1] / (2 * T);

    float *agg = nullptr, *dis = nullptr;
    int *dcnt = nullptr, *offs = nullptr, *cur = nullptr, *slist = nullptr;
    int *bsum = nullptr, *bexcl = nullptr;
    cudaGetSymbolAddress((void**)(&agg),   g_agg);
    cudaGetSymbolAddress((void**)(&dcnt),  g_dcnt);
    cudaGetSymbolAddress((void**)(&dis),   g_dis);
    cudaGetSymbolAddress((void**)(&offs),  g_offs);
    cudaGetSymbolAddress((void**)(&cur),   g_cur);
    cudaGetSymbolAddress((void**)(&slist), g_slist);
    cudaGetSymbolAddress((void**)(&bsum),  g_bsum);
    cudaGetSymbolAddress((void**)(&bexcl), g_bexcl);

    const int n    = T * N;
    const int nblk = (n + 1023) / 1024;

    k_deg_zero<<<(n + 255) / 256, 256>>>(dcnt, n);
    {
        int total = T * E;
        k_deg_count<<<(total + 255) / 256, 256>>>(edges, dcnt, N, E, T);
    }
    k_scan_reduce<<<nblk, 256>>>(dcnt, bsum, n);
    k_scan_bsum<<<1, 512>>>(bsum, bexcl, nblk);
    k_scan_final<<<nblk, 256>>>(dcnt, bexcl, offs, cur, dis, n);
    {
        int total = T * E;
        k_fill<<<(total + 255) / 256, 256>>>(edges, cur, slist, N, E, T);
    }
    {
        int warps = n;
        int blocks = (warps + 7) / 8;
        k_gather<<<blocks, 256>>>(x, dis, offs, dcnt, slist, agg, N, T);
    }
    k_gemm_mma<<<(N + 127) / 128, 256>>>(agg, W, b, out, N, T);
}